// round 5
// baseline (speedup 1.0000x reference)
#include <cuda_runtime.h>
#include <cstdint>
#include <math.h>

// Problem constants
static constexpr int MTOT = 32 * 1024;   // B*N = 32768 rows
static constexpr int KDIM = 1024;        // 2H
static constexpr int HDIM = 512;         // H
static constexpr float DT_STEP = 0.1f;

// Scratch activations (allocation-free rule: __device__ globals)
__device__ float g_buf0[(size_t)MTOT * KDIM];
__device__ float g_buf1[(size_t)MTOT * KDIM];

// Tiling
static constexpr int BM = 128, BN = 128, BK = 32;
static constexpr int AS   = BK + 4;          // 36 floats: A smem row stride (conflict-free frag LDS)
static constexpr int WSTR = BN + 8;          // 136 floats: W smem row stride (conflict-free frag LDS)
static constexpr int SA_FLOATS    = BM * AS;            // 4608
static constexpr int SW_FLOATS    = BK * WSTR;          // 4352
static constexpr int STAGE_FLOATS = SA_FLOATS + SW_FLOATS;   // 8960
static constexpr int SMEM_BYTES   = 2 * STAGE_FLOATS * 4;    // 71680

__device__ __forceinline__ uint32_t f2tf(float x) {
    uint32_t r;
    asm("cvt.rna.tf32.f32 %0, %1;" : "=r"(r) : "f"(x));
    return r;
}

__device__ __forceinline__ void cp16(uint32_t s, const void* g) {
    asm volatile("cp.async.cg.shared.global [%0], [%1], 16;\n" :: "r"(s), "l"(g));
}
__device__ __forceinline__ void cp_commit() {
    asm volatile("cp.async.commit_group;\n");
}
template<int N> __device__ __forceinline__ void cp_wait() {
    asm volatile("cp.async.wait_group %0;\n" :: "n"(N));
}

__device__ __forceinline__ void mma_tf32(float d[4], const uint32_t a[4], const uint32_t b[2]) {
    asm volatile(
        "mma.sync.aligned.m16n8k8.row.col.f32.tf32.tf32.f32 "
        "{%0,%1,%2,%3},{%4,%5,%6,%7},{%8,%9},{%0,%1,%2,%3};\n"
        : "+f"(d[0]), "+f"(d[1]), "+f"(d[2]), "+f"(d[3])
        : "r"(a[0]), "r"(a[1]), "r"(a[2]), "r"(a[3]), "r"(b[0]), "r"(b[1]));
}

// EPI: 0 -> out = resid + DT*tanh(acc+bias)   (resid comes from same A source)
//      1 -> out = relu(acc+bias)
//      2 -> out = tanh(acc+bias)
// CONCAT: A (and resid) columns [0,512) from A0, [512,1024) from A1
template<int NOUT, int EPI, bool CONCAT>
__global__ void __launch_bounds__(128, 1)
gemm_fused(const float* __restrict__ A0, const float* __restrict__ A1,
           const float* __restrict__ W,  const float* __restrict__ bias,
           float* __restrict__ out)
{
    extern __shared__ float smem[];
    const int tid  = threadIdx.x;
    const int lane = tid & 31;
    const int warp = tid >> 5;
    const int wm = warp >> 1, wn = warp & 1;       // 2x2 warps, 64x64 each
    const int bm = blockIdx.y * BM;
    const int bn = blockIdx.x * BN;

    const uint32_t sbase = (uint32_t)__cvta_generic_to_shared(smem);

    float acc[4][8][4];
    #pragma unroll
    for (int mi = 0; mi < 4; mi++)
        #pragma unroll
        for (int ni = 0; ni < 8; ni++)
            #pragma unroll
            for (int r = 0; r < 4; r++)
                acc[mi][ni][r] = 0.f;

    auto load_stage = [&](int k0, int stage) {
        uint32_t sA = sbase + (uint32_t)(stage * STAGE_FLOATS * 4);
        uint32_t sW = sA + (uint32_t)(SA_FLOATS * 4);
        // A tile: BM x BK floats = 1024 float4, 8 per thread
        #pragma unroll
        for (int i = 0; i < 8; i++) {
            int idx = tid + i * 128;
            int r  = idx >> 3;
            int kq = idx & 7;
            int gk = k0 + kq * 4;
            const float* src;
            if (CONCAT) {
                src = (gk < HDIM) ? (A0 + (size_t)(bm + r) * HDIM + gk)
                                  : (A1 + (size_t)(bm + r) * HDIM + (gk - HDIM));
            } else {
                src = A0 + (size_t)(bm + r) * KDIM + gk;
            }
            cp16(sA + (uint32_t)(r * AS + kq * 4) * 4, src);
        }
        // W tile: BK x BN floats = 1024 float4, 8 per thread
        #pragma unroll
        for (int i = 0; i < 8; i++) {
            int idx = tid + i * 128;
            int r  = idx >> 5;
            int nq = idx & 31;
            cp16(sW + (uint32_t)(r * WSTR + nq * 4) * 4,
                 W + (size_t)(k0 + r) * NOUT + bn + nq * 4);
        }
        cp_commit();
    };

    load_stage(0, 0);

    constexpr int KT = KDIM / BK;  // 32
    #pragma unroll 1
    for (int kt = 0; kt < KT; kt++) {
        const int s = kt & 1;
        if (kt + 1 < KT) {
            load_stage((kt + 1) * BK, s ^ 1);
            cp_wait<1>();
        } else {
            cp_wait<0>();
        }
        __syncthreads();

        const float* sAp = smem + s * STAGE_FLOATS;
        const float* sWp = sAp + SA_FLOATS;

        #pragma unroll
        for (int ks = 0; ks < 4; ks++) {
            uint32_t af[4][4];
            #pragma unroll
            for (int mi = 0; mi < 4; mi++) {
                int r = wm * 64 + mi * 16 + (lane >> 2);
                int c = ks * 8 + (lane & 3);
                af[mi][0] = f2tf(sAp[r * AS + c]);
                af[mi][1] = f2tf(sAp[(r + 8) * AS + c]);
                af[mi][2] = f2tf(sAp[r * AS + c + 4]);
                af[mi][3] = f2tf(sAp[(r + 8) * AS + c + 4]);
            }
            uint32_t bfr[8][2];
            #pragma unroll
            for (int ni = 0; ni < 8; ni++) {
                int k = ks * 8 + (lane & 3);
                int n = wn * 64 + ni * 8 + (lane >> 2);
                bfr[ni][0] = f2tf(sWp[k * WSTR + n]);
                bfr[ni][1] = f2tf(sWp[(k + 4) * WSTR + n]);
            }
            #pragma unroll
            for (int mi = 0; mi < 4; mi++)
                #pragma unroll
                for (int ni = 0; ni < 8; ni++)
                    mma_tf32(acc[mi][ni], af[mi], bfr[ni]);
        }
        __syncthreads();
    }

    // Epilogue: bias + activation (+ residual), float2 stores
    #pragma unroll
    for (int mi = 0; mi < 4; mi++) {
        const int row0 = bm + wm * 64 + mi * 16 + (lane >> 2);
        #pragma unroll
        for (int ni = 0; ni < 8; ni++) {
            const int col = bn + wn * 64 + ni * 8 + (lane & 3) * 2;
            const float b0 = bias[col];
            const float b1 = bias[col + 1];
            #pragma unroll
            for (int h = 0; h < 2; h++) {
                const int row = row0 + h * 8;
                float v0 = acc[mi][ni][h * 2 + 0] + b0;
                float v1 = acc[mi][ni][h * 2 + 1] + b1;
                if (EPI == 0) {
                    const float* src;
                    if (CONCAT) {
                        src = (col < HDIM) ? (A0 + (size_t)row * HDIM + col)
                                           : (A1 + (size_t)row * HDIM + (col - HDIM));
                    } else {
                        src = A0 + (size_t)row * KDIM + col;
                    }
                    v0 = src[0] + DT_STEP * tanhf(v0);
                    v1 = src[1] + DT_STEP * tanhf(v1);
                } else if (EPI == 1) {
                    v0 = fmaxf(v0, 0.f);
                    v1 = fmaxf(v1, 0.f);
                } else {
                    v0 = tanhf(v0);
                    v1 = tanhf(v1);
                }
                *reinterpret_cast<float2*>(out + (size_t)row * NOUT + col) =
                    make_float2(v0, v1);
            }
        }
    }
}

extern "C" void kernel_launch(void* const* d_in, const int* in_sizes, int n_in,
                              void* d_out, int out_size)
{
    const float* inp = (const float*)d_in[0];
    const float* hz  = (const float*)d_in[1];
    const float* Wf  = (const float*)d_in[2];
    const float* bf  = (const float*)d_in[3];
    const float* W1  = (const float*)d_in[4];
    const float* b1  = (const float*)d_in[5];
    const float* W2  = (const float*)d_in[6];
    const float* b2  = (const float*)d_in[7];
    float* out = (float*)d_out;

    float *buf0 = nullptr, *buf1 = nullptr;
    cudaGetSymbolAddress((void**)&buf0, g_buf0);
    cudaGetSymbolAddress((void**)&buf1, g_buf1);

    cudaFuncSetAttribute(gemm_fused<1024, 0, true >, cudaFuncAttributeMaxDynamicSharedMemorySize, SMEM_BYTES);
    cudaFuncSetAttribute(gemm_fused<1024, 0, false>, cudaFuncAttributeMaxDynamicSharedMemorySize, SMEM_BYTES);
    cudaFuncSetAttribute(gemm_fused<1024, 1, false>, cudaFuncAttributeMaxDynamicSharedMemorySize, SMEM_BYTES);
    cudaFuncSetAttribute(gemm_fused<512,  2, false>, cudaFuncAttributeMaxDynamicSharedMemorySize, SMEM_BYTES);

    dim3 blk(128);
    dim3 g1(1024 / BN, MTOT / BM);  // (8, 256)
    dim3 g4(512  / BN, MTOT / BM);  // (4, 256)

    // Layer 1: h1 = concat(inp,hz) + DT*tanh(concat @ Wf + bf)
    gemm_fused<1024, 0, true ><<<g1, blk, SMEM_BYTES>>>(inp,  hz,      Wf, bf, buf0);
    // Layer 2: h2 = h1 + DT*tanh(h1 @ Wf + bf)
    gemm_fused<1024, 0, false><<<g1, blk, SMEM_BYTES>>>(buf0, nullptr, Wf, bf, buf1);
    // Layer 3: h3 = relu(h2 @ W1 + b1)
    gemm_fused<1024, 1, false><<<g1, blk, SMEM_BYTES>>>(buf1, nullptr, W1, b1, buf0);
    // Layer 4: out = tanh(h3 @ W2 + b2)
    gemm_fused<512,  2, false><<<g4, blk, SMEM_BYTES>>>(buf0, nullptr, W2, b2, out);
}

// round 10
// speedup vs baseline: 1.0645x; 1.0645x over previous
#include <cuda_runtime.h>
#include <cstdint>
#include <math.h>

// Problem constants
static constexpr int MTOT = 32 * 1024;   // B*N = 32768 rows
static constexpr int KDIM = 1024;        // 2H
static constexpr int HDIM = 512;         // H
static constexpr float DT_STEP = 0.1f;

// Scratch (allocation-free rule: __device__ globals)
__device__ float g_cat [(size_t)MTOT * KDIM];   // rounded concat(inp,hz); later reused
__device__ float g_buf0[(size_t)MTOT * KDIM];   // full-precision h1
__device__ float g_buf1[(size_t)MTOT * KDIM];   // rounded activations
__device__ float g_Wf[KDIM * KDIM];             // tf32-rounded weights
__device__ float g_W1[KDIM * KDIM];
__device__ float g_W2[KDIM * HDIM];

// Tiling
static constexpr int BM = 128, BN = 128, BK = 32;
static constexpr int STAGES = 3;
static constexpr int AS   = BK + 4;          // 36 floats: A smem row stride (conflict-free frag LDS)
static constexpr int WSTR = BN + 8;          // 136 floats: W smem row stride (conflict-free frag LDS)
static constexpr int SA_FLOATS    = BM * AS;                  // 4608
static constexpr int SW_FLOATS    = BK * WSTR;                // 4352
static constexpr int STAGE_FLOATS = SA_FLOATS + SW_FLOATS;    // 8960
static constexpr int SMEM_BYTES   = STAGES * STAGE_FLOATS * 4; // 107520

__device__ __forceinline__ uint32_t f2tf(float x) {
    uint32_t r;
    asm("cvt.rna.tf32.f32 %0, %1;" : "=r"(r) : "f"(x));
    return r;
}
__device__ __forceinline__ float roundtf(float x) { return __uint_as_float(f2tf(x)); }

__device__ __forceinline__ void cp16(uint32_t s, const void* g) {
    asm volatile("cp.async.cg.shared.global [%0], [%1], 16;\n" :: "r"(s), "l"(g));
}
__device__ __forceinline__ void cp_commit() {
    asm volatile("cp.async.commit_group;\n");
}
template<int N> __device__ __forceinline__ void cp_wait() {
    asm volatile("cp.async.wait_group %0;\n" :: "n"(N));
}

__device__ __forceinline__ void mma_tf32(float d[4], const uint32_t a[4], const uint32_t b[2]) {
    asm volatile(
        "mma.sync.aligned.m16n8k8.row.col.f32.tf32.tf32.f32 "
        "{%0,%1,%2,%3},{%4,%5,%6,%7},{%8,%9},{%0,%1,%2,%3};\n"
        : "+f"(d[0]), "+f"(d[1]), "+f"(d[2]), "+f"(d[3])
        : "r"(a[0]), "r"(a[1]), "r"(a[2]), "r"(a[3]), "r"(b[0]), "r"(b[1]));
}

// ---------------- pre-passes -----------------------------------------------

// dst = tf32_round(src), vectorized float4
__global__ void round_tf32_k(const float4* __restrict__ src, float4* __restrict__ dst, int n4) {
    int i = blockIdx.x * blockDim.x + threadIdx.x;
    if (i < n4) {
        float4 v = src[i];
        v.x = roundtf(v.x); v.y = roundtf(v.y); v.z = roundtf(v.z); v.w = roundtf(v.w);
        dst[i] = v;
    }
}

// dst[M][1024] = tf32_round(concat(inp[M][512], hz[M][512]))
__global__ void cat_round_k(const float4* __restrict__ inp, const float4* __restrict__ hz,
                            float4* __restrict__ dst) {
    int i = blockIdx.x * blockDim.x + threadIdx.x;   // over MTOT*256 float4s
    int row = i >> 8;
    int c   = i & 255;
    float4 v = (c < 128) ? inp[row * 128 + c] : hz[row * 128 + (c - 128)];
    v.x = roundtf(v.x); v.y = roundtf(v.y); v.z = roundtf(v.z); v.w = roundtf(v.w);
    dst[i] = v;
}

// ---------------- fused GEMM -----------------------------------------------
// A is pre-rounded tf32 values stored as fp32, stride KDIM.
// EPI: 0 -> v = resid + DT*tanh(acc+bias)   (resid from R0 [, R1 if RCAT])
//      1 -> v = relu(acc+bias)
//      2 -> v = tanh(acc+bias)
// ROUND_OUT: store tf32-rounded v to out (else raw).
// DUAL: additionally store raw v to out2.
template<int NOUT, int EPI, bool RCAT, bool ROUND_OUT, bool DUAL>
__global__ void __launch_bounds__(128, 1)
gemm_fused(const float* __restrict__ A,
           const float* __restrict__ R0, const float* __restrict__ R1,
           const float* __restrict__ W,  const float* __restrict__ bias,
           float* __restrict__ out, float* __restrict__ out2)
{
    extern __shared__ float smem[];
    const int tid  = threadIdx.x;
    const int lane = tid & 31;
    const int warp = tid >> 5;
    const int wm = warp >> 1, wn = warp & 1;       // 2x2 warps, 64x64 each
    const int bm = blockIdx.y * BM;
    const int bn = blockIdx.x * BN;

    const uint32_t sbase = (uint32_t)__cvta_generic_to_shared(smem);

    float acc[4][8][4];
    #pragma unroll
    for (int mi = 0; mi < 4; mi++)
        #pragma unroll
        for (int ni = 0; ni < 8; ni++)
            #pragma unroll
            for (int r = 0; r < 4; r++)
                acc[mi][ni][r] = 0.f;

    auto load_stage = [&](int k0, int stage) {
        uint32_t sA = sbase + (uint32_t)(stage * STAGE_FLOATS * 4);
        uint32_t sW = sA + (uint32_t)(SA_FLOATS * 4);
        // A tile: BM x BK floats = 1024 float4, 8 per thread
        #pragma unroll
        for (int i = 0; i < 8; i++) {
            int idx = tid + i * 128;
            int r  = idx >> 3;
            int kq = idx & 7;
            cp16(sA + (uint32_t)(r * AS + kq * 4) * 4,
                 A + (size_t)(bm + r) * KDIM + k0 + kq * 4);
        }
        // W tile: BK x BN floats = 1024 float4, 8 per thread
        #pragma unroll
        for (int i = 0; i < 8; i++) {
            int idx = tid + i * 128;
            int r  = idx >> 5;
            int nq = idx & 31;
            cp16(sW + (uint32_t)(r * WSTR + nq * 4) * 4,
                 W + (size_t)(k0 + r) * NOUT + bn + nq * 4);
        }
        cp_commit();
    };

    load_stage(0, 0);
    load_stage(BK, 1);

    constexpr int KT = KDIM / BK;  // 32
    int cs = 0;                    // compute stage
    #pragma unroll 1
    for (int kt = 0; kt < KT; kt++) {
        if (kt + 2 < KT) {
            int ls = cs + 2; if (ls >= STAGES) ls -= STAGES;
            load_stage((kt + 2) * BK, ls);
        } else {
            cp_commit();           // keep group accounting uniform
        }
        cp_wait<2>();
        __syncthreads();

        const float* sAp = smem + cs * STAGE_FLOATS;
        const float* sWp = sAp + SA_FLOATS;

        #pragma unroll
        for (int ks = 0; ks < 4; ks++) {
            uint32_t af[4][4];
            #pragma unroll
            for (int mi = 0; mi < 4; mi++) {
                int r = wm * 64 + mi * 16 + (lane >> 2);
                int c = ks * 8 + (lane & 3);
                af[mi][0] = __float_as_uint(sAp[r * AS + c]);
                af[mi][1] = __float_as_uint(sAp[(r + 8) * AS + c]);
                af[mi][2] = __float_as_uint(sAp[r * AS + c + 4]);
                af[mi][3] = __float_as_uint(sAp[(r + 8) * AS + c + 4]);
            }
            uint32_t bfr[8][2];
            #pragma unroll
            for (int ni = 0; ni < 8; ni++) {
                int k = ks * 8 + (lane & 3);
                int n = wn * 64 + ni * 8 + (lane >> 2);
                bfr[ni][0] = __float_as_uint(sWp[k * WSTR + n]);
                bfr[ni][1] = __float_as_uint(sWp[(k + 4) * WSTR + n]);
            }
            #pragma unroll
            for (int mi = 0; mi < 4; mi++)
                #pragma unroll
                for (int ni = 0; ni < 8; ni++)
                    mma_tf32(acc[mi][ni], af[mi], bfr[ni]);
        }
        __syncthreads();
        cs++; if (cs >= STAGES) cs = 0;
    }

    // Epilogue: bias + activation (+ residual), float2 stores
    #pragma unroll
    for (int mi = 0; mi < 4; mi++) {
        const int row0 = bm + wm * 64 + mi * 16 + (lane >> 2);
        #pragma unroll
        for (int ni = 0; ni < 8; ni++) {
            const int col = bn + wn * 64 + ni * 8 + (lane & 3) * 2;
            const float b0 = bias[col];
            const float b1 = bias[col + 1];
            #pragma unroll
            for (int h = 0; h < 2; h++) {
                const int row = row0 + h * 8;
                float v0 = acc[mi][ni][h * 2 + 0] + b0;
                float v1 = acc[mi][ni][h * 2 + 1] + b1;
                if (EPI == 0) {
                    const float* rsrc;
                    if (RCAT) {
                        rsrc = (col < HDIM) ? (R0 + (size_t)row * HDIM + col)
                                            : (R1 + (size_t)row * HDIM + (col - HDIM));
                    } else {
                        rsrc = R0 + (size_t)row * KDIM + col;
                    }
                    v0 = rsrc[0] + DT_STEP * tanhf(v0);
                    v1 = rsrc[1] + DT_STEP * tanhf(v1);
                } else if (EPI == 1) {
                    v0 = fmaxf(v0, 0.f);
                    v1 = fmaxf(v1, 0.f);
                } else {
                    v0 = tanhf(v0);
                    v1 = tanhf(v1);
                }
                float s0 = ROUND_OUT ? roundtf(v0) : v0;
                float s1 = ROUND_OUT ? roundtf(v1) : v1;
                *reinterpret_cast<float2*>(out + (size_t)row * NOUT + col) =
                    make_float2(s0, s1);
                if (DUAL) {
                    *reinterpret_cast<float2*>(out2 + (size_t)row * NOUT + col) =
                        make_float2(v0, v1);
                }
            }
        }
    }
}

extern "C" void kernel_launch(void* const* d_in, const int* in_sizes, int n_in,
                              void* d_out, int out_size)
{
    const float* inp = (const float*)d_in[0];
    const float* hz  = (const float*)d_in[1];
    const float* Wf  = (const float*)d_in[2];
    const float* bf  = (const float*)d_in[3];
    const float* W1  = (const float*)d_in[4];
    const float* b1  = (const float*)d_in[5];
    const float* W2  = (const float*)d_in[6];
    const float* b2  = (const float*)d_in[7];
    float* out = (float*)d_out;

    float *cat_p, *buf0, *buf1, *wf_p, *w1_p, *w2_p;
    cudaGetSymbolAddress((void**)&cat_p, g_cat);
    cudaGetSymbolAddress((void**)&buf0,  g_buf0);
    cudaGetSymbolAddress((void**)&buf1,  g_buf1);
    cudaGetSymbolAddress((void**)&wf_p,  g_Wf);
    cudaGetSymbolAddress((void**)&w1_p,  g_W1);
    cudaGetSymbolAddress((void**)&w2_p,  g_W2);

    cudaFuncSetAttribute(gemm_fused<1024, 0, true,  true,  true >, cudaFuncAttributeMaxDynamicSharedMemorySize, SMEM_BYTES);
    cudaFuncSetAttribute(gemm_fused<1024, 0, false, true,  false>, cudaFuncAttributeMaxDynamicSharedMemorySize, SMEM_BYTES);
    cudaFuncSetAttribute(gemm_fused<1024, 1, false, true,  false>, cudaFuncAttributeMaxDynamicSharedMemorySize, SMEM_BYTES);
    cudaFuncSetAttribute(gemm_fused<512,  2, false, false, false>, cudaFuncAttributeMaxDynamicSharedMemorySize, SMEM_BYTES);

    // --- pre-passes: tf32-round weights, build rounded concat input --------
    {
        int n4 = KDIM * KDIM / 4;
        round_tf32_k<<<(n4 + 255) / 256, 256>>>((const float4*)Wf, (float4*)wf_p, n4);
        round_tf32_k<<<(n4 + 255) / 256, 256>>>((const float4*)W1, (float4*)w1_p, n4);
        int n4b = KDIM * HDIM / 4;
        round_tf32_k<<<(n4b + 255) / 256, 256>>>((const float4*)W2, (float4*)w2_p, n4b);
        cat_round_k<<<MTOT, 256>>>((const float4*)inp, (const float4*)hz, (float4*)cat_p);
    }

    dim3 blk(128);
    dim3 g1(1024 / BN, MTOT / BM);  // (8, 256)
    dim3 g4(512  / BN, MTOT / BM);  // (4, 256)

    // L1: h1 = concat + DT*tanh(cat @ Wf + bf); write rounded->buf1, full->buf0
    gemm_fused<1024, 0, true,  true,  true ><<<g1, blk, SMEM_BYTES>>>(cat_p, inp,  hz, wf_p, bf, buf1, buf0);
    // L2: h2 = h1 + DT*tanh(h1r @ Wf + bf); resid = full h1; write rounded->g_cat
    gemm_fused<1024, 0, false, true,  false><<<g1, blk, SMEM_BYTES>>>(buf1, buf0, nullptr, wf_p, bf, cat_p, nullptr);
    // L3: h3 = relu(h2 @ W1 + b1); write rounded->buf1
    gemm_fused<1024, 1, false, true,  false><<<g1, blk, SMEM_BYTES>>>(cat_p, nullptr, nullptr, w1_p, b1, buf1, nullptr);
    // L4: out = tanh(h3 @ W2 + b2); raw fp32 output
    gemm_fused<512,  2, false, false, false><<<g4, blk, SMEM_BYTES>>>(buf1, nullptr, nullptr, w2_p, b2, out, nullptr);
}

// round 12
// speedup vs baseline: 1.4690x; 1.3800x over previous
#include <cuda_runtime.h>
#include <cuda_fp16.h>
#include <cstdint>
#include <math.h>

// Problem constants
static constexpr int MTOT = 32 * 1024;   // B*N rows
static constexpr int KDIM = 1024;        // 2H
static constexpr int HDIM = 512;         // H
static constexpr float DT_STEP = 0.1f;

// Scratch (allocation-free rule: __device__ globals)
__device__ __align__(16) __half g_h0[(size_t)MTOT * KDIM];  // fp16 activations (ping)
__device__ __align__(16) __half g_h1[(size_t)MTOT * KDIM];  // fp16 activations (pong)
__device__ float g_f0[(size_t)MTOT * KDIM];                 // full-precision h1 (residual)
__device__ __align__(16) __half g_WfT[KDIM * KDIM];         // weights, transposed [N][K], fp16
__device__ __align__(16) __half g_W1T[KDIM * KDIM];
__device__ __align__(16) __half g_W2T[HDIM * KDIM];

// Tiling
static constexpr int BM = 128, BN = 256, BK = 32;   // BK in fp16 elements
static constexpr int STAGES = 3;
static constexpr int KT = KDIM / BK;                // 32 k-tiles
static constexpr int ASTR = BK + 8;                 // 40 halves = 80B row stride (ldmatrix conflict-free)
static constexpr int A_BYTES = BM * ASTR * 2;       // 10240
static constexpr int B_BYTES = BN * ASTR * 2;       // 20480
static constexpr int STAGE_BYTES = A_BYTES + B_BYTES;          // 30720
static constexpr int SMEM_BYTES  = STAGES * STAGE_BYTES;       // 92160

// ---------------- helpers ---------------------------------------------------
__device__ __forceinline__ void cp16(uint32_t s, const void* g) {
    asm volatile("cp.async.cg.shared.global [%0], [%1], 16;\n" :: "r"(s), "l"(g));
}
__device__ __forceinline__ void cp_commit() {
    asm volatile("cp.async.commit_group;\n");
}
template<int N> __device__ __forceinline__ void cp_wait() {
    asm volatile("cp.async.wait_group %0;\n" :: "n"(N));
}
__device__ __forceinline__ void ldm_x4(uint32_t r[4], uint32_t a) {
    asm volatile("ldmatrix.sync.aligned.m8n8.x4.shared.b16 {%0,%1,%2,%3}, [%4];"
                 : "=r"(r[0]), "=r"(r[1]), "=r"(r[2]), "=r"(r[3]) : "r"(a));
}
__device__ __forceinline__ void mma_f16(float d[4], const uint32_t a[4],
                                        uint32_t b0, uint32_t b1) {
    asm volatile(
        "mma.sync.aligned.m16n8k16.row.col.f32.f16.f16.f32 "
        "{%0,%1,%2,%3},{%4,%5,%6,%7},{%8,%9},{%0,%1,%2,%3};\n"
        : "+f"(d[0]), "+f"(d[1]), "+f"(d[2]), "+f"(d[3])
        : "r"(a[0]), "r"(a[1]), "r"(a[2]), "r"(a[3]), "r"(b0), "r"(b1));
}

// ---------------- pre-passes -----------------------------------------------

// WT[n][k] = fp16(W[k][n]);  W is [K x N] row-major fp32
__global__ void transp_h_k(const float* __restrict__ src, __half* __restrict__ dst,
                           int K, int N) {
    __shared__ float t[32][33];
    int kb = blockIdx.x * 32, nb = blockIdx.y * 32;
    int tx = threadIdx.x;
    for (int i = threadIdx.y; i < 32; i += 8)
        t[i][tx] = src[(size_t)(kb + i) * N + nb + tx];
    __syncthreads();
    for (int i = threadIdx.y; i < 32; i += 8)
        dst[(size_t)(nb + i) * K + kb + tx] = __float2half_rn(t[tx][i]);
}

// dst[M][1024] = fp16(concat(inp[M][512], hz[M][512]))
__global__ void cat_h_k(const float4* __restrict__ inp, const float4* __restrict__ hz,
                        uint2* __restrict__ dst) {
    int i = blockIdx.x * blockDim.x + threadIdx.x;   // over MTOT*256 float4 groups
    int row = i >> 8;
    int c   = i & 255;
    float4 v = (c < 128) ? inp[row * 128 + c] : hz[row * 128 + (c - 128)];
    __half2 p0 = __floats2half2_rn(v.x, v.y);
    __half2 p1 = __floats2half2_rn(v.z, v.w);
    uint2 u;
    u.x = *reinterpret_cast<uint32_t*>(&p0);
    u.y = *reinterpret_cast<uint32_t*>(&p1);
    dst[i] = u;
}

// ---------------- fused fp16 tensor-core GEMM -------------------------------
// A: [MTOT x KDIM] fp16.  WT: [NOUT x KDIM] fp16 (N-major rows, K contiguous).
// EPI: 0 -> v = resid + DT*tanh(acc+bias)   (resid fp32 from R0 [, R1 if RCAT])
//      1 -> v = relu(acc+bias)
//      2 -> v = tanh(acc+bias)
// OUT_HALF: store fp16 to out (activation buffer); else fp32.
// DUAL: additionally store full fp32 v to out2 (stride KDIM).
template<int NOUT, int EPI, bool RCAT, bool OUT_HALF, bool DUAL>
__global__ void __launch_bounds__(256, 1)
gemm_h(const __half* __restrict__ A,
       const float* __restrict__ R0, const float* __restrict__ R1,
       const __half* __restrict__ WT, const float* __restrict__ bias,
       void* __restrict__ out, float* __restrict__ out2)
{
    extern __shared__ char smem_raw[];
    const uint32_t st0 = (uint32_t)__cvta_generic_to_shared(smem_raw);

    const int tid  = threadIdx.x;
    const int lane = tid & 31;
    const int warp = tid >> 5;
    const int wm = warp >> 2;            // 0..1  (rows of 64)
    const int wn = warp & 3;             // 0..3  (cols of 64)
    const int bm = blockIdx.y * BM;
    const int bn = blockIdx.x * BN;

    float acc[4][8][4];
    #pragma unroll
    for (int mi = 0; mi < 4; mi++)
        #pragma unroll
        for (int ni = 0; ni < 8; ni++)
            #pragma unroll
            for (int r = 0; r < 4; r++)
                acc[mi][ni][r] = 0.f;

    auto load_stage = [&](int t, int stage) {
        uint32_t uS = st0 + (uint32_t)(stage * STAGE_BYTES);
        uint32_t uB = uS + A_BYTES;
        const int k0 = t * BK;
        // A tile: 128 rows x 64B  (512 cp16, 2/thread)
        #pragma unroll
        for (int i = 0; i < 2; i++) {
            int idx = tid + i * 256;
            int r = idx >> 2, c = idx & 3;
            cp16(uS + (uint32_t)(r * 80 + c * 16),
                 A + (size_t)(bm + r) * KDIM + k0 + c * 8);
        }
        // B tile: 256 rows x 64B  (1024 cp16, 4/thread)
        #pragma unroll
        for (int i = 0; i < 4; i++) {
            int idx = tid + i * 256;
            int r = idx >> 2, c = idx & 3;
            cp16(uB + (uint32_t)(r * 80 + c * 16),
                 WT + (size_t)(bn + r) * KDIM + k0 + c * 8);
        }
        cp_commit();
    };

    load_stage(0, 0);
    load_stage(1, 1);

    // Per-thread ldmatrix address components (bytes, within stage)
    const uint32_t aOff = (uint32_t)(((lane & 7) + ((lane >> 3) & 1) * 8 + wm * 64) * 80
                                     + (lane >> 4) * 16);
    const uint32_t bOff = (uint32_t)(A_BYTES
                                     + ((lane & 7) + (lane >> 4) * 8 + wn * 64) * 80
                                     + ((lane >> 3) & 1) * 16);

    int cs = 0;
    #pragma unroll 1
    for (int kt = 0; kt < KT; kt++) {
        if (kt + 2 < KT) {
            int ls = cs + 2; if (ls >= STAGES) ls -= STAGES;
            load_stage(kt + 2, ls);
        } else {
            cp_commit();
        }
        cp_wait<2>();
        __syncthreads();

        const uint32_t uS = st0 + (uint32_t)(cs * STAGE_BYTES);
        #pragma unroll
        for (int ks = 0; ks < 2; ks++) {             // two K=16 slices per BK=32
            uint32_t af[4][4];
            #pragma unroll
            for (int mi = 0; mi < 4; mi++)
                ldm_x4(af[mi], uS + aOff + (uint32_t)(mi * 16 * 80 + ks * 32));
            uint32_t bf[4][4];
            #pragma unroll
            for (int np = 0; np < 4; np++)
                ldm_x4(bf[np], uS + bOff + (uint32_t)(np * 16 * 80 + ks * 32));
            #pragma unroll
            for (int mi = 0; mi < 4; mi++)
                #pragma unroll
                for (int ni = 0; ni < 8; ni++)
                    mma_f16(acc[mi][ni], af[mi],
                            bf[ni >> 1][(ni & 1) * 2], bf[ni >> 1][(ni & 1) * 2 + 1]);
        }
        __syncthreads();
        cs++; if (cs >= STAGES) cs = 0;
    }

    // ---- epilogue: bias + activation (+ residual) -------------------------
    #pragma unroll
    for (int mi = 0; mi < 4; mi++) {
        const int row0 = bm + wm * 64 + mi * 16 + (lane >> 2);
        #pragma unroll
        for (int ni = 0; ni < 8; ni++) {
            const int col = bn + wn * 64 + ni * 8 + (lane & 3) * 2;
            const float b0 = bias[col];
            const float b1 = bias[col + 1];
            #pragma unroll
            for (int h = 0; h < 2; h++) {
                const int row = row0 + h * 8;
                float v0 = acc[mi][ni][h * 2 + 0] + b0;
                float v1 = acc[mi][ni][h * 2 + 1] + b1;
                if (EPI == 0) {
                    const float* rsrc;
                    if (RCAT) {
                        rsrc = (col < HDIM) ? (R0 + (size_t)row * HDIM + col)
                                            : (R1 + (size_t)row * HDIM + (col - HDIM));
                    } else {
                        rsrc = R0 + (size_t)row * KDIM + col;
                    }
                    v0 = rsrc[0] + DT_STEP * tanhf(v0);
                    v1 = rsrc[1] + DT_STEP * tanhf(v1);
                } else if (EPI == 1) {
                    v0 = fmaxf(v0, 0.f);
                    v1 = fmaxf(v1, 0.f);
                } else {
                    v0 = tanhf(v0);
                    v1 = tanhf(v1);
                }
                if (OUT_HALF) {
                    *reinterpret_cast<__half2*>((__half*)out + (size_t)row * NOUT + col) =
                        __floats2half2_rn(v0, v1);
                } else {
                    *reinterpret_cast<float2*>((float*)out + (size_t)row * NOUT + col) =
                        make_float2(v0, v1);
                }
                if (DUAL) {
                    *reinterpret_cast<float2*>(out2 + (size_t)row * KDIM + col) =
                        make_float2(v0, v1);
                }
            }
        }
    }
}

// ---------------- launch ----------------------------------------------------

extern "C" void kernel_launch(void* const* d_in, const int* in_sizes, int n_in,
                              void* d_out, int out_size)
{
    const float* inp = (const float*)d_in[0];
    const float* hz  = (const float*)d_in[1];
    const float* Wf  = (const float*)d_in[2];
    const float* bf  = (const float*)d_in[3];
    const float* W1  = (const float*)d_in[4];
    const float* b1  = (const float*)d_in[5];
    const float* W2  = (const float*)d_in[6];
    const float* b2  = (const float*)d_in[7];
    float* out = (float*)d_out;

    __half *h0, *h1, *wfT, *w1T, *w2T;
    float *f0;
    cudaGetSymbolAddress((void**)&h0,  g_h0);
    cudaGetSymbolAddress((void**)&h1,  g_h1);
    cudaGetSymbolAddress((void**)&f0,  g_f0);
    cudaGetSymbolAddress((void**)&wfT, g_WfT);
    cudaGetSymbolAddress((void**)&w1T, g_W1T);
    cudaGetSymbolAddress((void**)&w2T, g_W2T);

    cudaFuncSetAttribute(gemm_h<1024, 0, true,  true,  true >, cudaFuncAttributeMaxDynamicSharedMemorySize, SMEM_BYTES);
    cudaFuncSetAttribute(gemm_h<1024, 0, false, true,  false>, cudaFuncAttributeMaxDynamicSharedMemorySize, SMEM_BYTES);
    cudaFuncSetAttribute(gemm_h<1024, 1, false, true,  false>, cudaFuncAttributeMaxDynamicSharedMemorySize, SMEM_BYTES);
    cudaFuncSetAttribute(gemm_h<512,  2, false, false, false>, cudaFuncAttributeMaxDynamicSharedMemorySize, SMEM_BYTES);

    // pre-passes: transpose+fp16 weights to [N][K]; fp16 concat input
    {
        dim3 tb(32, 8);
        transp_h_k<<<dim3(KDIM / 32, KDIM / 32), tb>>>(Wf, wfT, KDIM, KDIM);
        transp_h_k<<<dim3(KDIM / 32, KDIM / 32), tb>>>(W1, w1T, KDIM, KDIM);
        transp_h_k<<<dim3(KDIM / 32, HDIM / 32), tb>>>(W2, w2T, KDIM, HDIM);
        cat_h_k<<<MTOT, 256>>>((const float4*)inp, (const float4*)hz, (uint2*)h0);
    }

    dim3 blk(256);
    dim3 g1(KDIM / BN, MTOT / BM);   // (4, 256)
    dim3 g4(HDIM / BN, MTOT / BM);   // (2, 256)

    // L1: h1 = concat + DT*tanh(cat @ Wf + bf); fp16->g_h1, fp32->g_f0
    gemm_h<1024, 0, true,  true,  true ><<<g1, blk, SMEM_BYTES>>>(h0, inp,  hz,      wfT, bf, h1, f0);
    // L2: h2 = h1 + DT*tanh(h1 @ Wf + bf); resid = fp32 h1; fp16->g_h0
    gemm_h<1024, 0, false, true,  false><<<g1, blk, SMEM_BYTES>>>(h1, f0,   nullptr, wfT, bf, h0, nullptr);
    // L3: h3 = relu(h2 @ W1 + b1); fp16->g_h1
    gemm_h<1024, 1, false, true,  false><<<g1, blk, SMEM_BYTES>>>(h0, nullptr, nullptr, w1T, b1, h1, nullptr);
    // L4: out = tanh(h3 @ W2 + b2); fp32 output
    gemm_h<512,  2, false, false, false><<<g4, blk, SMEM_BYTES>>>(h1, nullptr, nullptr, w2T, b2, out, nullptr);
}

// round 14
// speedup vs baseline: 1.9891x; 1.3541x over previous
#include <cuda_runtime.h>
#include <cuda_fp16.h>
#include <cstdint>
#include <math.h>

// Problem constants
static constexpr int MTOT = 32 * 1024;   // B*N rows
static constexpr int KDIM = 1024;        // 2H
static constexpr int HDIM = 512;         // H
static constexpr float DT_STEP = 0.1f;

// Tiling
static constexpr int BM = 128, BN = 256, BK = 32;   // BK in fp16 elements
static constexpr int STAGES = 8;
static constexpr int KT = KDIM / BK;                // 32 k-tiles
static constexpr int A_TILE = BM * BK * 2;          // 8192 B  (contiguous in gmem)
static constexpr int B_TILE = BN * BK * 2;          // 16384 B (contiguous in gmem)
static constexpr int STAGE_BYTES = A_TILE + B_TILE; // 24576
static constexpr int CTRL = 1024;                   // mbarriers live here
static constexpr int SMEM_BYTES = CTRL + STAGES * STAGE_BYTES;  // 197632

// Scratch (allocation-free rule: __device__ globals)
// Activations: tiled fp16 [mblk][kt][128][32], swizzled within tile.
__device__ __align__(16) __half g_h0[(size_t)MTOT * KDIM];
__device__ __align__(16) __half g_h1[(size_t)MTOT * KDIM];
__device__ float g_f0[(size_t)MTOT * KDIM];          // fp32 h1 residual, row-major
// Weights: tiled fp16 [nblk][kt][256][32], swizzled within tile.
__device__ __align__(16) __half g_WfT[KDIM * KDIM];
__device__ __align__(16) __half g_W1T[KDIM * KDIM];
__device__ __align__(16) __half g_W2T[HDIM * KDIM];

// Swizzle within a tile row: physical 16B-chunk = logical chunk ^ ((row>>1)&3).
// Rows are 64B (32 halves). Conflict-free for 8-row ldmatrix phases.

// ---------------- helpers ---------------------------------------------------
__device__ __forceinline__ void ldm_x4(uint32_t r[4], uint32_t a) {
    asm volatile("ldmatrix.sync.aligned.m8n8.x4.shared.b16 {%0,%1,%2,%3}, [%4];"
                 : "=r"(r[0]), "=r"(r[1]), "=r"(r[2]), "=r"(r[3]) : "r"(a));
}
__device__ __forceinline__ void mma_f16(float d[4], const uint32_t a[4],
                                        uint32_t b0, uint32_t b1) {
    asm volatile(
        "mma.sync.aligned.m16n8k16.row.col.f32.f16.f16.f32 "
        "{%0,%1,%2,%3},{%4,%5,%6,%7},{%8,%9},{%0,%1,%2,%3};\n"
        : "+f"(d[0]), "+f"(d[1]), "+f"(d[2]), "+f"(d[3])
        : "r"(a[0]), "r"(a[1]), "r"(a[2]), "r"(a[3]), "r"(b0), "r"(b1));
}
__device__ __forceinline__ void mbar_init(uint32_t a, uint32_t cnt) {
    asm volatile("mbarrier.init.shared.b64 [%0], %1;" :: "r"(a), "r"(cnt) : "memory");
}
__device__ __forceinline__ void mbar_expect_tx(uint32_t a, uint32_t bytes) {
    asm volatile("mbarrier.arrive.expect_tx.shared.b64 _, [%0], %1;"
                 :: "r"(a), "r"(bytes) : "memory");
}
__device__ __forceinline__ void mbar_wait(uint32_t a, uint32_t parity) {
    asm volatile(
        "{\n\t.reg .pred P;\n\t"
        "WL%=:\n\t"
        "mbarrier.try_wait.parity.acquire.cta.shared::cta.b64 P, [%0], %1, 0x989680;\n\t"
        "@P bra.uni WD%=;\n\t"
        "bra.uni WL%=;\n\t"
        "WD%=:\n\t}"
        :: "r"(a), "r"(parity) : "memory");
}
__device__ __forceinline__ void bulk_g2s(uint32_t dst, const void* src,
                                         uint32_t bytes, uint32_t mbar) {
    asm volatile(
        "cp.async.bulk.shared::cluster.global.mbarrier::complete_tx::bytes "
        "[%0], [%1], %2, [%3];"
        :: "r"(dst), "l"(src), "r"(bytes), "r"(mbar) : "memory");
}
__device__ __forceinline__ float tanh_fast(float x) {      // HW tanh, err ~5e-4 abs
    float y;
    asm("tanh.approx.f32 %0, %1;" : "=f"(y) : "f"(x));
    return y;
}

// ---------------- pre-passes -----------------------------------------------

// Weights: W [K][N] fp32 row-major -> tiled swizzled fp16 [nblk][kt][256][32]
__global__ void transp_h_k(const float* __restrict__ src, __half* __restrict__ dst,
                           int K, int N) {
    __shared__ float t[32][33];                  // t[k][n]
    int kb = blockIdx.x * 32, nb = blockIdx.y * 32;
    int tx = threadIdx.x, ty = threadIdx.y;
    for (int i = ty; i < 32; i += 8)
        t[i][tx] = src[(size_t)(kb + i) * N + nb + tx];
    __syncthreads();
    int w = ty * 32 + tx;
    if (w < 128) {
        int n_i = w >> 2, ch = w & 3;            // n row, 16B chunk (8 halves)
        int n = nb + n_i;
        __half h[8];
        #pragma unroll
        for (int j = 0; j < 8; j++)
            h[j] = __float2half_rn(t[ch * 8 + j][n_i]);
        int r = n & 255;
        size_t byte = ((size_t)((n >> 8) * KT + (kb >> 5)) << 14)    // *16384
                      + ((size_t)r << 6)
                      + ((uint32_t)(ch ^ ((r >> 1) & 3)) << 4);
        *reinterpret_cast<uint4*>((char*)dst + byte) = *reinterpret_cast<uint4*>(h);
    }
}

// Input: concat(inp,hz) fp32 -> tiled swizzled fp16 activations
__global__ void cat_h_k(const float4* __restrict__ inp, const float4* __restrict__ hz,
                        __half* __restrict__ dst) {
    int i = blockIdx.x * blockDim.x + threadIdx.x;   // over MTOT*256 float4s
    int row = i >> 8;
    int c4  = i & 255;
    int k   = c4 * 4;
    float4 v = (c4 < 128) ? inp[row * 128 + c4] : hz[row * 128 + (c4 - 128)];
    __half h[4] = { __float2half_rn(v.x), __float2half_rn(v.y),
                    __float2half_rn(v.z), __float2half_rn(v.w) };
    int mblk = row >> 7, r = row & 127, kt = k >> 5, kk = k & 31;
    size_t byte = ((size_t)(mblk * KT + kt) << 13)                   // *8192
                  + ((size_t)r << 6)
                  + ((uint32_t)((kk >> 3) ^ ((r >> 1) & 3)) << 4)
                  + ((uint32_t)(kk & 7) << 1);
    *reinterpret_cast<uint2*>((char*)dst + byte) = *reinterpret_cast<uint2*>(h);
}

// ---------------- fused fp16 tensor-core GEMM (TMA-bulk pipeline) -----------
// A: tiled fp16 activations. WT: tiled fp16 weights.
// EPI: 0 -> v = resid + DT*tanh(acc+bias)   (resid fp32 from R0 [, R1 if RCAT])
//      1 -> v = relu(acc+bias)
//      2 -> v = tanh(acc+bias)      (precise)
// OUT_HALF: store fp16 to tiled 'out'; else fp32 row-major.
// DUAL: additionally store fp32 v to out2 row-major (stride KDIM).
template<int NOUT, int EPI, bool RCAT, bool OUT_HALF, bool DUAL>
__global__ void __launch_bounds__(256, 1)
gemm_h(const __half* __restrict__ A,
       const float* __restrict__ R0, const float* __restrict__ R1,
       const __half* __restrict__ WT, const float* __restrict__ bias,
       void* __restrict__ out, float* __restrict__ out2)
{
    extern __shared__ char smem_raw[];
    const uint32_t sbase = (uint32_t)__cvta_generic_to_shared(smem_raw);
    const uint32_t st0   = sbase + CTRL;

    const int tid  = threadIdx.x;
    const int lane = tid & 31;
    const int warp = tid >> 5;
    const int wm = warp >> 2;            // 0..1  (64-row groups)
    const int wn = warp & 3;             // 0..3  (64-col groups)
    const int mblk = blockIdx.y;
    const int nblk = blockIdx.x;
    const int bm = mblk * BM;
    const int bn = nblk * BN;

    auto mb = [&](int s) -> uint32_t { return sbase + 16 * s; };

    if (tid == 0) {
        #pragma unroll
        for (int s = 0; s < STAGES; s++) mbar_init(mb(s), 1);
    }
    __syncthreads();

    const char* gA = (const char*)A  + ((size_t)mblk * KT) * A_TILE;
    const char* gB = (const char*)WT + ((size_t)nblk * KT) * B_TILE;

    auto issue = [&](int t) {
        int s = t & 7;
        uint32_t dst = st0 + (uint32_t)(s * STAGE_BYTES);
        mbar_expect_tx(mb(s), STAGE_BYTES);
        bulk_g2s(dst,          gA + (size_t)t * A_TILE, A_TILE, mb(s));
        bulk_g2s(dst + A_TILE, gB + (size_t)t * B_TILE, B_TILE, mb(s));
    };

    if (tid == 0) {
        #pragma unroll
        for (int t = 0; t < STAGES; t++) issue(t);
    }

    float acc[4][8][4];
    #pragma unroll
    for (int mi = 0; mi < 4; mi++)
        #pragma unroll
        for (int ni = 0; ni < 8; ni++)
            #pragma unroll
            for (int r = 0; r < 4; r++)
                acc[mi][ni][r] = 0.f;

    // Per-thread ldmatrix row geometry (offsets within tile, swizzle selectors)
    const int aRow = wm * 64 + (lane & 15);
    const uint32_t aSel = (uint32_t)((aRow >> 1) & 3);
    const uint32_t aHi  = (uint32_t)(lane >> 4);            // 0/1: 16B chunk parity
    const uint32_t aOff = (uint32_t)(aRow * 64);
    const int bRow = wn * 64 + (lane & 7) + ((lane >> 4) << 3);
    const uint32_t bSel = (uint32_t)((bRow >> 1) & 3);
    const uint32_t bHi  = (uint32_t)((lane >> 3) & 1);
    const uint32_t bOff = (uint32_t)(A_TILE + bRow * 64);

    #pragma unroll 1
    for (int kt = 0; kt < KT; kt++) {
        const int s = kt & 7;
        mbar_wait(mb(s), (kt >> 3) & 1);

        const uint32_t uS = st0 + (uint32_t)(s * STAGE_BYTES);
        #pragma unroll
        for (int ks = 0; ks < 2; ks++) {            // two K=16 slices per BK=32
            const uint32_t aCh = ((uint32_t)(ks * 2) + aHi) ^ aSel;  // 0..3
            const uint32_t bCh = ((uint32_t)(ks * 2) + bHi) ^ bSel;
            uint32_t af[4][4];
            #pragma unroll
            for (int mi = 0; mi < 4; mi++)
                ldm_x4(af[mi], uS + aOff + (uint32_t)(mi * 1024) + (aCh << 4));
            uint32_t bf[4][4];
            #pragma unroll
            for (int np = 0; np < 4; np++)
                ldm_x4(bf[np], uS + bOff + (uint32_t)(np * 1024) + (bCh << 4));
            #pragma unroll
            for (int mi = 0; mi < 4; mi++)
                #pragma unroll
                for (int ni = 0; ni < 8; ni++)
                    mma_f16(acc[mi][ni], af[mi],
                            bf[ni >> 1][(ni & 1) * 2], bf[ni >> 1][(ni & 1) * 2 + 1]);
        }
        __syncthreads();                             // all warps done with stage s
        if (tid == 0 && kt + STAGES < KT) issue(kt + STAGES);
    }

    // ---- epilogue: bias + activation (+ residual) -------------------------
    #pragma unroll
    for (int mi = 0; mi < 4; mi++) {
        const int row0 = bm + wm * 64 + mi * 16 + (lane >> 2);
        #pragma unroll
        for (int ni = 0; ni < 8; ni++) {
            const int col = bn + wn * 64 + ni * 8 + (lane & 3) * 2;
            const float b0 = bias[col];
            const float b1 = bias[col + 1];
            #pragma unroll
            for (int h = 0; h < 2; h++) {
                const int row = row0 + h * 8;
                float v0 = acc[mi][ni][h * 2 + 0] + b0;
                float v1 = acc[mi][ni][h * 2 + 1] + b1;
                if (EPI == 0) {
                    const float* rsrc;
                    if (RCAT) {
                        rsrc = (col < HDIM) ? (R0 + (size_t)row * HDIM + col)
                                            : (R1 + (size_t)row * HDIM + (col - HDIM));
                    } else {
                        rsrc = R0 + (size_t)row * KDIM + col;
                    }
                    v0 = rsrc[0] + DT_STEP * tanh_fast(v0);
                    v1 = rsrc[1] + DT_STEP * tanh_fast(v1);
                } else if (EPI == 1) {
                    v0 = fmaxf(v0, 0.f);
                    v1 = fmaxf(v1, 0.f);
                } else {
                    v0 = tanhf(v0);
                    v1 = tanhf(v1);
                }
                if (OUT_HALF) {
                    // tiled swizzled fp16 activation layout
                    int mb2 = row >> 7, r = row & 127, kt2 = col >> 5, kk = col & 31;
                    size_t byte = ((size_t)(mb2 * KT + kt2) << 13)
                                  + ((size_t)r << 6)
                                  + ((uint32_t)((kk >> 3) ^ ((r >> 1) & 3)) << 4)
                                  + ((uint32_t)(kk & 7) << 1);
                    *reinterpret_cast<__half2*>((char*)out + byte) =
                        __floats2half2_rn(v0, v1);
                } else {
                    *reinterpret_cast<float2*>((float*)out + (size_t)row * NOUT + col) =
                        make_float2(v0, v1);
                }
                if (DUAL) {
                    *reinterpret_cast<float2*>(out2 + (size_t)row * KDIM + col) =
                        make_float2(v0, v1);
                }
            }
        }
    }
}

// ---------------- launch ----------------------------------------------------

extern "C" void kernel_launch(void* const* d_in, const int* in_sizes, int n_in,
                              void* d_out, int out_size)
{
    const float* inp = (const float*)d_in[0];
    const float* hz  = (const float*)d_in[1];
    const float* Wf  = (const float*)d_in[2];
    const float* bf  = (const float*)d_in[3];
    const float* W1  = (const float*)d_in[4];
    const float* b1  = (const float*)d_in[5];
    const float* W2  = (const float*)d_in[6];
    const float* b2  = (const float*)d_in[7];
    float* out = (float*)d_out;

    __half *h0, *h1, *wfT, *w1T, *w2T;
    float *f0;
    cudaGetSymbolAddress((void**)&h0,  g_h0);
    cudaGetSymbolAddress((void**)&h1,  g_h1);
    cudaGetSymbolAddress((void**)&f0,  g_f0);
    cudaGetSymbolAddress((void**)&wfT, g_WfT);
    cudaGetSymbolAddress((void**)&w1T, g_W1T);
    cudaGetSymbolAddress((void**)&w2T, g_W2T);

    cudaFuncSetAttribute(gemm_h<1024, 0, true,  true,  true >, cudaFuncAttributeMaxDynamicSharedMemorySize, SMEM_BYTES);
    cudaFuncSetAttribute(gemm_h<1024, 0, false, true,  false>, cudaFuncAttributeMaxDynamicSharedMemorySize, SMEM_BYTES);
    cudaFuncSetAttribute(gemm_h<1024, 1, false, true,  false>, cudaFuncAttributeMaxDynamicSharedMemorySize, SMEM_BYTES);
    cudaFuncSetAttribute(gemm_h<512,  2, false, false, false>, cudaFuncAttributeMaxDynamicSharedMemorySize, SMEM_BYTES);

    // pre-passes: weights -> tiled swizzled fp16 [N][K]; concat input -> tiled fp16
    {
        dim3 tb(32, 8);
        transp_h_k<<<dim3(KDIM / 32, KDIM / 32), tb>>>(Wf, wfT, KDIM, KDIM);
        transp_h_k<<<dim3(KDIM / 32, KDIM / 32), tb>>>(W1, w1T, KDIM, KDIM);
        transp_h_k<<<dim3(KDIM / 32, HDIM / 32), tb>>>(W2, w2T, KDIM, HDIM);
        cat_h_k<<<MTOT, 256>>>((const float4*)inp, (const float4*)hz, h0);
    }

    dim3 blk(256);
    dim3 g1(KDIM / BN, MTOT / BM);   // (4, 256)
    dim3 g4(HDIM / BN, MTOT / BM);   // (2, 256)

    // L1: h1 = concat + DT*tanh(cat @ Wf + bf); fp16 tiled->g_h1, fp32->g_f0
    gemm_h<1024, 0, true,  true,  true ><<<g1, blk, SMEM_BYTES>>>(h0, inp,  hz,      wfT, bf, h1, f0);
    // L2: h2 = h1 + DT*tanh(h1 @ Wf + bf); resid = fp32 h1; fp16 tiled->g_h0
    gemm_h<1024, 0, false, true,  false><<<g1, blk, SMEM_BYTES>>>(h1, f0,   nullptr, wfT, bf, h0, nullptr);
    // L3: h3 = relu(h2 @ W1 + b1); fp16 tiled->g_h1
    gemm_h<1024, 1, false, true,  false><<<g1, blk, SMEM_BYTES>>>(h0, nullptr, nullptr, w1T, b1, h1, nullptr);
    // L4: out = tanh(h3 @ W2 + b2); fp32 row-major output
    gemm_h<512,  2, false, false, false><<<g4, blk, SMEM_BYTES>>>(h1, nullptr, nullptr, w2T, b2, out, nullptr);
}

// round 17
// speedup vs baseline: 2.0189x; 1.0150x over previous
#include <cuda_runtime.h>
#include <cuda_fp16.h>
#include <cstdint>
#include <math.h>

// Problem constants
static constexpr int MTOT = 32 * 1024;   // B*N rows
static constexpr int KDIM = 1024;        // 2H
static constexpr int HDIM = 512;         // H
static constexpr float DT_STEP = 0.1f;

// Tiling
static constexpr int BM = 128, BN = 256, BK = 64;   // BK in fp16 elements
static constexpr int STAGES = 4;
static constexpr int KT = KDIM / BK;                // 16 k-tiles
static constexpr int A_TILE = BM * BK * 2;          // 16384 B (contiguous in gmem)
static constexpr int B_TILE = BN * BK * 2;          // 32768 B (contiguous in gmem)
static constexpr int STAGE_BYTES = A_TILE + B_TILE; // 49152
static constexpr int CTRL = 1024;                   // mbarriers live here
static constexpr int SMEM_BYTES = CTRL + STAGES * STAGE_BYTES;  // 197632

static constexpr int NTHREADS = 288;     // 8 compute warps + 1 producer warp

// Scratch (allocation-free rule: __device__ globals)
// Activations: tiled fp16 [mblk][kt][128 rows][64 halves], SW128-swizzled rows.
__device__ __align__(16) __half g_h0[(size_t)MTOT * KDIM];
__device__ __align__(16) __half g_h1[(size_t)MTOT * KDIM];
__device__ float g_f0[(size_t)MTOT * KDIM];          // fp32 h1 residual, row-major
// Weights: tiled fp16 [nblk][kt][256 rows][64 halves], SW128-swizzled rows.
__device__ __align__(16) __half g_WfT[KDIM * KDIM];
__device__ __align__(16) __half g_W1T[KDIM * KDIM];
__device__ __align__(16) __half g_W2T[HDIM * KDIM];

// Row = 128 B (64 halves) = 8 chunks of 16 B. physical_chunk = logical ^ (row & 7).
// Conflict-free for every 8-consecutive-row ldmatrix phase.

// ---------------- helpers ---------------------------------------------------
__device__ __forceinline__ void ldm_x4(uint32_t r[4], uint32_t a) {
    asm volatile("ldmatrix.sync.aligned.m8n8.x4.shared.b16 {%0,%1,%2,%3}, [%4];"
                 : "=r"(r[0]), "=r"(r[1]), "=r"(r[2]), "=r"(r[3]) : "r"(a));
}
__device__ __forceinline__ void mma_f16(float d[4], const uint32_t a[4],
                                        uint32_t b0, uint32_t b1) {
    asm volatile(
        "mma.sync.aligned.m16n8k16.row.col.f32.f16.f16.f32 "
        "{%0,%1,%2,%3},{%4,%5,%6,%7},{%8,%9},{%0,%1,%2,%3};\n"
        : "+f"(d[0]), "+f"(d[1]), "+f"(d[2]), "+f"(d[3])
        : "r"(a[0]), "r"(a[1]), "r"(a[2]), "r"(a[3]), "r"(b0), "r"(b1));
}
__device__ __forceinline__ void mbar_init(uint32_t a, uint32_t cnt) {
    asm volatile("mbarrier.init.shared.b64 [%0], %1;" :: "r"(a), "r"(cnt) : "memory");
}
__device__ __forceinline__ void mbar_expect_tx(uint32_t a, uint32_t bytes) {
    asm volatile("mbarrier.arrive.expect_tx.shared.b64 _, [%0], %1;"
                 :: "r"(a), "r"(bytes) : "memory");
}
__device__ __forceinline__ void mbar_arrive(uint32_t a) {
    asm volatile("mbarrier.arrive.shared.b64 _, [%0];" :: "r"(a) : "memory");
}
__device__ __forceinline__ void mbar_wait(uint32_t a, uint32_t parity) {
    asm volatile(
        "{\n\t.reg .pred P;\n\t"
        "WL%=:\n\t"
        "mbarrier.try_wait.parity.acquire.cta.shared::cta.b64 P, [%0], %1, 0x989680;\n\t"
        "@P bra.uni WD%=;\n\t"
        "bra.uni WL%=;\n\t"
        "WD%=:\n\t}"
        :: "r"(a), "r"(parity) : "memory");
}
__device__ __forceinline__ void bulk_g2s(uint32_t dst, const void* src,
                                         uint32_t bytes, uint32_t mbar) {
    asm volatile(
        "cp.async.bulk.shared::cluster.global.mbarrier::complete_tx::bytes "
        "[%0], [%1], %2, [%3];"
        :: "r"(dst), "l"(src), "r"(bytes), "r"(mbar) : "memory");
}
__device__ __forceinline__ float tanh_fast(float x) {      // HW tanh, err ~5e-4 abs
    float y;
    asm("tanh.approx.f32 %0, %1;" : "=f"(y) : "f"(x));
    return y;
}

// ---------------- pre-passes -----------------------------------------------

// Weights: W [K][N] fp32 row-major -> tiled swizzled fp16 [nblk][kt][256][64]
__global__ void transp_h_k(const float* __restrict__ src, __half* __restrict__ dst,
                           int K, int N) {
    __shared__ float t[32][33];                  // t[k][n]
    int kb = blockIdx.x * 32, nb = blockIdx.y * 32;
    int tx = threadIdx.x, ty = threadIdx.y;
    for (int i = ty; i < 32; i += 8)
        t[i][tx] = src[(size_t)(kb + i) * N + nb + tx];
    __syncthreads();
    int w = ty * 32 + tx;
    if (w < 128) {
        int n_i = w >> 2, chl = w & 3;           // n row, local 16B chunk
        int n = nb + n_i;
        __half h[8];
        #pragma unroll
        for (int j = 0; j < 8; j++)
            h[j] = __float2half_rn(t[chl * 8 + j][n_i]);
        int r  = n & 255;
        int ch = ((kb & 63) >> 3) + chl;         // chunk within 64-half tile row
        size_t byte = ((size_t)((n >> 8) * KT + (kb >> 6)) << 15)   // *32768
                      + ((size_t)r << 7)
                      + ((uint32_t)(ch ^ (r & 7)) << 4);
        *reinterpret_cast<uint4*>((char*)dst + byte) = *reinterpret_cast<uint4*>(h);
    }
}

// Input: concat(inp,hz) fp32 -> tiled swizzled fp16 activations
__global__ void cat_h_k(const float4* __restrict__ inp, const float4* __restrict__ hz,
                        __half* __restrict__ dst) {
    int i = blockIdx.x * blockDim.x + threadIdx.x;   // over MTOT*256 float4s
    int row = i >> 8;
    int c4  = i & 255;
    int k   = c4 * 4;
    float4 v = (c4 < 128) ? inp[row * 128 + c4] : hz[row * 128 + (c4 - 128)];
    __half h[4] = { __float2half_rn(v.x), __float2half_rn(v.y),
                    __float2half_rn(v.z), __float2half_rn(v.w) };
    int mblk = row >> 7, r = row & 127, kt = k >> 6, kk = k & 63;
    size_t byte = ((size_t)(mblk * KT + kt) << 14)                   // *16384
                  + ((size_t)r << 7)
                  + ((uint32_t)((kk >> 3) ^ (r & 7)) << 4)
                  + ((uint32_t)(kk & 7) << 1);
    *reinterpret_cast<uint2*>((char*)dst + byte) = *reinterpret_cast<uint2*>(h);
}

// ---------------- fused fp16 tensor-core GEMM (warp-specialized) ------------
// A: tiled fp16 activations. WT: tiled fp16 weights.
// EPI: 0 -> v = resid + DT*tanh(acc+bias)   (resid fp32 from R0 [, R1 if RCAT])
//      1 -> v = relu(acc+bias)
//      2 -> v = tanh(acc+bias)      (precise)
// OUT_HALF: store fp16 to tiled 'out'; else fp32 row-major.
// DUAL: additionally store fp32 v to out2 row-major (stride KDIM).
template<int NOUT, int EPI, bool RCAT, bool OUT_HALF, bool DUAL>
__global__ void __launch_bounds__(NTHREADS, 1)
gemm_h(const __half* __restrict__ A,
       const float* __restrict__ R0, const float* __restrict__ R1,
       const __half* __restrict__ WT, const float* __restrict__ bias,
       void* __restrict__ out, float* __restrict__ out2)
{
    extern __shared__ char smem_raw[];
    const uint32_t sbase = (uint32_t)__cvta_generic_to_shared(smem_raw);
    const uint32_t st0   = sbase + CTRL;

    const int tid  = threadIdx.x;
    const int lane = tid & 31;
    const int warp = tid >> 5;
    const int mblk = blockIdx.y;
    const int nblk = blockIdx.x;

    auto fullb  = [&](int s) -> uint32_t { return sbase + 16 * s; };
    auto emptyb = [&](int s) -> uint32_t { return sbase + 64 + 16 * s; };

    if (tid == 0) {
        #pragma unroll
        for (int s = 0; s < STAGES; s++) {
            mbar_init(fullb(s), 1);      // producer's expect_tx is the single arrive
            mbar_init(emptyb(s), 8);     // ONE arrive per compute warp
        }
    }
    __syncthreads();

    if (warp == 8) {
        // ---------------- producer warp --------------------------------
        if (lane == 0) {
            const char* gA = (const char*)A  + ((size_t)mblk * KT) * A_TILE;
            const char* gB = (const char*)WT + ((size_t)nblk * KT) * B_TILE;
            #pragma unroll 1
            for (int t = 0; t < KT; t++) {
                const int s = t & 3;
                const int u = t >> 2;
                if (u > 0) mbar_wait(emptyb(s), (u & 1) ^ 1);
                uint32_t dst = st0 + (uint32_t)(s * STAGE_BYTES);
                mbar_expect_tx(fullb(s), STAGE_BYTES);
                bulk_g2s(dst,          gA + (size_t)t * A_TILE, A_TILE, fullb(s));
                bulk_g2s(dst + A_TILE, gB + (size_t)t * B_TILE, B_TILE, fullb(s));
            }
        }
        return;
    }

    // ---------------- compute warps (0..7) ---------------------------------
    const int wm = warp >> 2;            // 0..1  (64-row groups)
    const int wn = warp & 3;             // 0..3  (64-col groups)
    const int bm = mblk * BM;
    const int bn = nblk * BN;

    float acc[4][8][4];
    #pragma unroll
    for (int mi = 0; mi < 4; mi++)
        #pragma unroll
        for (int ni = 0; ni < 8; ni++)
            #pragma unroll
            for (int r = 0; r < 4; r++)
                acc[mi][ni][r] = 0.f;

    // Per-thread ldmatrix row geometry (offsets within tile, swizzle selectors)
    const int aRow = wm * 64 + (lane & 15);
    const uint32_t aSel = (uint32_t)(aRow & 7);
    const uint32_t aHi  = (uint32_t)(lane >> 4);            // 16B chunk parity
    const uint32_t aOff = (uint32_t)(aRow * 128);
    const int bRow = wn * 64 + (lane & 7) + ((lane >> 4) << 3);
    const uint32_t bSel = (uint32_t)(bRow & 7);
    const uint32_t bHi  = (uint32_t)((lane >> 3) & 1);
    const uint32_t bOff = (uint32_t)(A_TILE + bRow * 128);

    #pragma unroll 1
    for (int kt = 0; kt < KT; kt++) {
        const int s = kt & 3;
        mbar_wait(fullb(s), (kt >> 2) & 1);

        const uint32_t uS = st0 + (uint32_t)(s * STAGE_BYTES);
        #pragma unroll
        for (int ks = 0; ks < 4; ks++) {            // four K=16 slices per BK=64
            const uint32_t aCh = ((uint32_t)(ks * 2) + aHi) ^ aSel;  // 0..7
            const uint32_t bCh = ((uint32_t)(ks * 2) + bHi) ^ bSel;
            uint32_t af[4][4];
            #pragma unroll
            for (int mi = 0; mi < 4; mi++)
                ldm_x4(af[mi], uS + aOff + (uint32_t)(mi * 2048) + (aCh << 4));
            uint32_t bf[4][4];
            #pragma unroll
            for (int np = 0; np < 4; np++)
                ldm_x4(bf[np], uS + bOff + (uint32_t)(np * 2048) + (bCh << 4));
            if (ks == 3 && lane == 0)
                mbar_arrive(emptyb(s));             // ONE arrive per warp: stage drained
            #pragma unroll
            for (int mi = 0; mi < 4; mi++)
                #pragma unroll
                for (int ni = 0; ni < 8; ni++)
                    mma_f16(acc[mi][ni], af[mi],
                            bf[ni >> 1][(ni & 1) * 2], bf[ni >> 1][(ni & 1) * 2 + 1]);
        }
    }

    // ---- epilogue: bias + activation (+ residual) -------------------------
    #pragma unroll
    for (int mi = 0; mi < 4; mi++) {
        const int row0 = bm + wm * 64 + mi * 16 + (lane >> 2);
        #pragma unroll
        for (int ni = 0; ni < 8; ni++) {
            const int col = bn + wn * 64 + ni * 8 + (lane & 3) * 2;
            const float b0 = bias[col];
            const float b1 = bias[col + 1];
            #pragma unroll
            for (int h = 0; h < 2; h++) {
                const int row = row0 + h * 8;
                float v0 = acc[mi][ni][h * 2 + 0] + b0;
                float v1 = acc[mi][ni][h * 2 + 1] + b1;
                if (EPI == 0) {
                    const float* rsrc;
                    if (RCAT) {
                        rsrc = (col < HDIM) ? (R0 + (size_t)row * HDIM + col)
                                            : (R1 + (size_t)row * HDIM + (col - HDIM));
                    } else {
                        rsrc = R0 + (size_t)row * KDIM + col;
                    }
                    v0 = rsrc[0] + DT_STEP * tanh_fast(v0);
                    v1 = rsrc[1] + DT_STEP * tanh_fast(v1);
                } else if (EPI == 1) {
                    v0 = fmaxf(v0, 0.f);
                    v1 = fmaxf(v1, 0.f);
                } else {
                    v0 = tanhf(v0);
                    v1 = tanhf(v1);
                }
                if (OUT_HALF) {
                    // tiled swizzled fp16 activation layout
                    int mb2 = row >> 7, r = row & 127, kt2 = col >> 6, kk = col & 63;
                    size_t byte = ((size_t)(mb2 * KT + kt2) << 14)
                                  + ((size_t)r << 7)
                                  + ((uint32_t)((kk >> 3) ^ (r & 7)) << 4)
                                  + ((uint32_t)(kk & 7) << 1);
                    *reinterpret_cast<__half2*>((char*)out + byte) =
                        __floats2half2_rn(v0, v1);
                } else {
                    *reinterpret_cast<float2*>((float*)out + (size_t)row * NOUT + col) =
                        make_float2(v0, v1);
                }
                if (DUAL) {
                    *reinterpret_cast<float2*>(out2 + (size_t)row * KDIM + col) =
                        make_float2(v0, v1);
                }
            }
        }
    }
}

// ---------------- launch ----------------------------------------------------

extern "C" void kernel_launch(void* const* d_in, const int* in_sizes, int n_in,
                              void* d_out, int out_size)
{
    const float* inp = (const float*)d_in[0];
    const float* hz  = (const float*)d_in[1];
    const float* Wf  = (const float*)d_in[2];
    const float* bf  = (const float*)d_in[3];
    const float* W1  = (const float*)d_in[4];
    const float* b1  = (const float*)d_in[5];
    const float* W2  = (const float*)d_in[6];
    const float* b2  = (const float*)d_in[7];
    float* out = (float*)d_out;

    __half *h0, *h1, *wfT, *w1T, *w2T;
    float *f0;
    cudaGetSymbolAddress((void**)&h0,  g_h0);
    cudaGetSymbolAddress((void**)&h1,  g_h1);
    cudaGetSymbolAddress((void**)&f0,  g_f0);
    cudaGetSymbolAddress((void**)&wfT, g_WfT);
    cudaGetSymbolAddress((void**)&w1T, g_W1T);
    cudaGetSymbolAddress((void**)&w2T, g_W2T);

    cudaFuncSetAttribute(gemm_h<1024, 0, true,  true,  true >, cudaFuncAttributeMaxDynamicSharedMemorySize, SMEM_BYTES);
    cudaFuncSetAttribute(gemm_h<1024, 0, false, true,  false>, cudaFuncAttributeMaxDynamicSharedMemorySize, SMEM_BYTES);
    cudaFuncSetAttribute(gemm_h<1024, 1, false, true,  false>, cudaFuncAttributeMaxDynamicSharedMemorySize, SMEM_BYTES);
    cudaFuncSetAttribute(gemm_h<512,  2, false, false, false>, cudaFuncAttributeMaxDynamicSharedMemorySize, SMEM_BYTES);

    // pre-passes: weights -> tiled swizzled fp16 [N][K]; concat input -> tiled fp16
    {
        dim3 tb(32, 8);
        transp_h_k<<<dim3(KDIM / 32, KDIM / 32), tb>>>(Wf, wfT, KDIM, KDIM);
        transp_h_k<<<dim3(KDIM / 32, KDIM / 32), tb>>>(W1, w1T, KDIM, KDIM);
        transp_h_k<<<dim3(KDIM / 32, HDIM / 32), tb>>>(W2, w2T, KDIM, HDIM);
        cat_h_k<<<MTOT, 256>>>((const float4*)inp, (const float4*)hz, h0);
    }

    dim3 blk(NTHREADS);
    dim3 g1(KDIM / BN, MTOT / BM);   // (4, 256)
    dim3 g4(HDIM / BN, MTOT / BM);   // (2, 256)

    // L1: h1 = concat + DT*tanh(cat @ Wf + bf); fp16 tiled->g_h1, fp32->g_f0
    gemm_h<1024, 0, true,  true,  true ><<<g1, blk, SMEM_BYTES>>>(h0, inp,  hz,      wfT, bf, h1, f0);
    // L2: h2 = h1 + DT*tanh(h1 @ Wf + bf); resid = fp32 h1; fp16 tiled->g_h0
    gemm_h<1024, 0, false, true,  false><<<g1, blk, SMEM_BYTES>>>(h1, f0,   nullptr, wfT, bf, h0, nullptr);
    // L3: h3 = relu(h2 @ W1 + b1); fp16 tiled->g_h1
    gemm_h<1024, 1, false, true,  false><<<g1, blk, SMEM_BYTES>>>(h0, nullptr, nullptr, w1T, b1, h1, nullptr);
    // L4: out = tanh(h3 @ W2 + b2); fp32 row-major output
    gemm_h<512,  2, false, false, false><<<g4, blk, SMEM_BYTES>>>(h1, nullptr, nullptr, w2T, b2, out, nullptr);
}